// round 2
// baseline (speedup 1.0000x reference)
#include <cuda_runtime.h>
#include <math.h>

// ---------------- problem dims (fixed) ----------------
#define NN 50000
#define EE 600000
#define FIN 128
#define HID 128
#define KH 8
#define DA 16
#define DV 16
#define DM 64
#define NCLS 40
#define GATE_IN (HID + DM + HID)   // 320
#define WO_IN  (HID + KH*DV)       // 256
#define SLOPE 0.1f

// ---------------- device scratch (no allocations allowed) ----------------
__device__ float g_h   [NN*HID];
__device__ float g_h2  [NN*HID];
__device__ float g_q   [NN*KH*DA];
__device__ float g_k   [NN*KH*DA];
__device__ float g_v   [NN*KH*DV];
__device__ float g_m   [NN*DM];
__device__ float g_score[EE*KH];       // reused as ex
__device__ float g_smax [NN*KH];
__device__ float g_denom[NN*KH];
__device__ float g_agg  [NN*KH*DV];
__device__ float g_maxpool[NN*DM];
__device__ float g_meansum[NN*HID];
__device__ float g_deg  [NN];
__device__ float g_gatein[NN*GATE_IN];
__device__ float g_gate  [NN*KH];
__device__ float g_woin  [NN*WO_IN];
__device__ float g_logits[NN*NCLS];

// ---------------- helpers ----------------
__device__ __forceinline__ void atomicMaxF(float* addr, float value) {
    if (value >= 0.0f) atomicMax((int*)addr, __float_as_int(value));
    else               atomicMin((unsigned int*)addr, __float_as_uint(value));
}

// ---------------- kernels ----------------
__global__ void init_layer_k(float* smax, float* denom, float* agg,
                             float* maxpool, float* meansum, float* deg) {
    int i = blockIdx.x * blockDim.x + threadIdx.x;
    if (i < NN*HID) { agg[i] = 0.f; meansum[i] = 0.f; }
    if (i < NN*DM)  maxpool[i] = -INFINITY;
    if (i < NN*KH)  { smax[i] = -INFINITY; denom[i] = 0.f; }
    if (i < NN)     deg[i] = 0.f;
}

// C[M,Nc] = A[M,Kc] @ B[Kc,Nc], row-major. act: 0 none, 1 leaky_relu, 2 sigmoid
#define BM 64
#define BN 64
#define BK 16
__global__ void sgemm_k(const float* __restrict__ A, const float* __restrict__ B,
                        float* __restrict__ C, int M, int Nc, int Kc, int act) {
    __shared__ float As[BK][BM+1];
    __shared__ float Bs[BK][BN];
    int tid = threadIdx.x;                 // 256 threads
    int tx = tid & 15, ty = tid >> 4;
    int rowBase = blockIdx.y * BM;
    int colBase = blockIdx.x * BN;
    float acc[4][4] = {};

    for (int k0 = 0; k0 < Kc; k0 += BK) {
        #pragma unroll
        for (int i = tid; i < BM*BK; i += 256) {
            int r = i >> 4, c = i & 15;    // BK=16
            int gr = rowBase + r, gc = k0 + c;
            As[c][r] = (gr < M && gc < Kc) ? A[(size_t)gr*Kc + gc] : 0.f;
        }
        #pragma unroll
        for (int i = tid; i < BK*BN; i += 256) {
            int r = i >> 6, c = i & 63;    // BN=64
            int gr = k0 + r, gc = colBase + c;
            Bs[r][c] = (gr < Kc && gc < Nc) ? B[(size_t)gr*Nc + gc] : 0.f;
        }
        __syncthreads();
        #pragma unroll
        for (int kk = 0; kk < BK; kk++) {
            float a[4], b[4];
            #pragma unroll
            for (int i = 0; i < 4; i++) a[i] = As[kk][ty*4 + i];
            #pragma unroll
            for (int j = 0; j < 4; j++) b[j] = Bs[kk][tx*4 + j];
            #pragma unroll
            for (int i = 0; i < 4; i++)
                #pragma unroll
                for (int j = 0; j < 4; j++)
                    acc[i][j] += a[i] * b[j];
        }
        __syncthreads();
    }
    #pragma unroll
    for (int i = 0; i < 4; i++) {
        int gr = rowBase + ty*4 + i;
        if (gr >= M) continue;
        #pragma unroll
        for (int j = 0; j < 4; j++) {
            int gc = colBase + tx*4 + j;
            if (gc >= Nc) continue;
            float vv = acc[i][j];
            if (act == 1) vv = vv > 0.f ? vv : SLOPE * vv;
            else if (act == 2) vv = 1.0f / (1.0f + expf(-vv));
            C[(size_t)gr*Nc + gc] = vv;
        }
    }
}

// score[e,h] = <q[dst,h,:], k[src,h,:]>, atomic segment max into smax
__global__ void edge_score_k(const float* __restrict__ q, const float* __restrict__ kk,
                             const int* __restrict__ src, const int* __restrict__ dst,
                             float* __restrict__ score, float* __restrict__ smax) {
    int idx = blockIdx.x * blockDim.x + threadIdx.x;
    if (idx >= EE*KH) return;
    int e = idx >> 3, h = idx & 7;
    int s = src[e], d = dst[e];
    const float4* qa = (const float4*)(q + (size_t)d*(KH*DA) + h*DA);
    const float4* ka = (const float4*)(kk + (size_t)s*(KH*DA) + h*DA);
    float acc = 0.f;
    #pragma unroll
    for (int i = 0; i < 4; i++) {
        float4 a = qa[i], b = ka[i];
        acc += a.x*b.x + a.y*b.y + a.z*b.z + a.w*b.w;
    }
    score[idx] = acc;
    atomicMaxF(&smax[d*KH + h], acc);
}

// ex = exp(score - smax[dst]); store in place; atomic segment sum into denom
__global__ void edge_exp_k(float* __restrict__ score, const float* __restrict__ smax,
                           const int* __restrict__ dst, float* __restrict__ denom) {
    int idx = blockIdx.x * blockDim.x + threadIdx.x;
    if (idx >= EE*KH) return;
    int e = idx >> 3, h = idx & 7;
    int d = dst[e];
    float ex = expf(score[idx] - smax[d*KH + h]);
    score[idx] = ex;
    atomicAdd(&denom[d*KH + h], ex);
}

// agg[dst,h,:] += alpha * v[src,h,:]
__global__ void edge_agg_k(const float* __restrict__ ex, const float* __restrict__ denom,
                           const float* __restrict__ v,
                           const int* __restrict__ src, const int* __restrict__ dst,
                           float* __restrict__ agg) {
    int idx = blockIdx.x * blockDim.x + threadIdx.x;
    if (idx >= EE*KH) return;
    int e = idx >> 3, h = idx & 7;
    int s = src[e], d = dst[e];
    float alpha = ex[idx] / (denom[d*KH + h] + 1e-16f);
    const float4* vp = (const float4*)(v + (size_t)s*(KH*DV) + h*DV);
    float* ap = agg + (size_t)d*(KH*DV) + h*DV;
    #pragma unroll
    for (int i = 0; i < 4; i++) {
        float4 vv = vp[i];
        atomicAdd(ap + i*4 + 0, alpha * vv.x);
        atomicAdd(ap + i*4 + 1, alpha * vv.y);
        atomicAdd(ap + i*4 + 2, alpha * vv.z);
        atomicAdd(ap + i*4 + 3, alpha * vv.w);
    }
}

// max-pool of m[src] (64), mean-sum of h[src] (128), degree
__global__ void edge_pool_k(const float* __restrict__ m, const float* __restrict__ h,
                            const int* __restrict__ src, const int* __restrict__ dst,
                            float* __restrict__ maxpool, float* __restrict__ meansum,
                            float* __restrict__ deg) {
    long long idx = (long long)blockIdx.x * blockDim.x + threadIdx.x;
    if (idx >= (long long)EE*DM) return;
    int e = (int)(idx >> 6), j = (int)(idx & 63);
    int s = src[e], d = dst[e];
    atomicMaxF(&maxpool[(size_t)d*DM + j], m[(size_t)s*DM + j]);
    atomicAdd(&meansum[(size_t)d*HID + j],      h[(size_t)s*HID + j]);
    atomicAdd(&meansum[(size_t)d*HID + 64 + j], h[(size_t)s*HID + 64 + j]);
    if (j == 0) atomicAdd(&deg[d], 1.0f);
}

// gate_in = [h | fix(maxpool) | meansum/max(deg,1)]
__global__ void gatein_k(const float* __restrict__ h, const float* __restrict__ maxpool,
                         const float* __restrict__ meansum, const float* __restrict__ deg,
                         float* __restrict__ gi) {
    long long idx = (long long)blockIdx.x * blockDim.x + threadIdx.x;
    if (idx >= (long long)NN*GATE_IN) return;
    int n = (int)(idx / GATE_IN), j = (int)(idx % GATE_IN);
    float val;
    if (j < HID) val = h[(size_t)n*HID + j];
    else if (j < HID + DM) {
        float mp = maxpool[(size_t)n*DM + (j - HID)];
        val = isfinite(mp) ? mp : 0.f;
    } else {
        float dg = deg[n];
        val = meansum[(size_t)n*HID + (j - HID - DM)] / fmaxf(dg, 1.0f);
    }
    gi[idx] = val;
}

// wo_in = [h | g[n,h_head] * agg[n, h_head, d]]
__global__ void woin_k(const float* __restrict__ h, const float* __restrict__ g,
                       const float* __restrict__ agg, float* __restrict__ wi) {
    long long idx = (long long)blockIdx.x * blockDim.x + threadIdx.x;
    if (idx >= (long long)NN*WO_IN) return;
    int n = (int)(idx >> 8), j = (int)(idx & 255);
    float val;
    if (j < HID) val = h[(size_t)n*HID + j];
    else {
        int jj = j - HID;                 // 0..127
        val = g[(size_t)n*KH + (jj >> 4)] * agg[(size_t)n*(KH*DV) + jj];
    }
    wi[idx] = val;
}

// row-wise log_softmax over 40 classes; one warp per row
__global__ void logsoftmax_k(const float* __restrict__ logits, float* __restrict__ out) {
    int row = blockIdx.x * 4 + (threadIdx.x >> 5);
    int lane = threadIdx.x & 31;
    if (row >= NN) return;
    const float* p = logits + (size_t)row * NCLS;
    float v0 = p[lane];
    float v1 = (lane < NCLS - 32) ? p[lane + 32] : -INFINITY;
    float mx = fmaxf(v0, v1);
    #pragma unroll
    for (int off = 16; off > 0; off >>= 1)
        mx = fmaxf(mx, __shfl_xor_sync(0xffffffffu, mx, off));
    float sm = expf(v0 - mx) + ((lane < NCLS - 32) ? expf(v1 - mx) : 0.f);
    #pragma unroll
    for (int off = 16; off > 0; off >>= 1)
        sm += __shfl_xor_sync(0xffffffffu, sm, off);
    float lse = mx + logf(sm);
    out[(size_t)row*NCLS + lane] = v0 - lse;
    if (lane < NCLS - 32) out[(size_t)row*NCLS + lane + 32] = v1 - lse;
}

// ---------------- host side ----------------
static inline void launch_gemm(const float* A, const float* B, float* C,
                               int M, int Nc, int Kc, int act) {
    dim3 grid((Nc + BN - 1) / BN, (M + BM - 1) / BM);
    sgemm_k<<<grid, 256>>>(A, B, C, M, Nc, Kc, act);
}

extern "C" void kernel_launch(void* const* d_in, const int* in_sizes, int n_in,
                              void* d_out, int out_size) {
    const float* x     = (const float*)d_in[0];
    const int*   ei    = (const int*)d_in[1];      // int32: JAX demotes int64
    const float* w_in  = (const float*)d_in[2];
    const float* w_out = (const float*)d_in[3];
    const float* Wq    = (const float*)d_in[4];
    const float* Wk    = (const float*)d_in[5];
    const float* Wv    = (const float*)d_in[6];
    const float* Wm    = (const float*)d_in[7];
    const float* Wg    = (const float*)d_in[8];
    const float* Wo    = (const float*)d_in[9];
    float* out = (float*)d_out;

    const int* src = ei;        // edge_index[0]
    const int* dst = ei + EE;   // edge_index[1]

    float *h, *h2, *q, *k, *v, *m, *score, *smax, *denom, *agg;
    float *maxpool, *meansum, *deg, *gatein, *gate, *woin, *logits;
    cudaGetSymbolAddress((void**)&h,       g_h);
    cudaGetSymbolAddress((void**)&h2,      g_h2);
    cudaGetSymbolAddress((void**)&q,       g_q);
    cudaGetSymbolAddress((void**)&k,       g_k);
    cudaGetSymbolAddress((void**)&v,       g_v);
    cudaGetSymbolAddress((void**)&m,       g_m);
    cudaGetSymbolAddress((void**)&score,   g_score);
    cudaGetSymbolAddress((void**)&smax,    g_smax);
    cudaGetSymbolAddress((void**)&denom,   g_denom);
    cudaGetSymbolAddress((void**)&agg,     g_agg);
    cudaGetSymbolAddress((void**)&maxpool, g_maxpool);
    cudaGetSymbolAddress((void**)&meansum, g_meansum);
    cudaGetSymbolAddress((void**)&deg,     g_deg);
    cudaGetSymbolAddress((void**)&gatein,  g_gatein);
    cudaGetSymbolAddress((void**)&gate,    g_gate);
    cudaGetSymbolAddress((void**)&woin,    g_woin);
    cudaGetSymbolAddress((void**)&logits,  g_logits);

    // h = x @ weight_in
    launch_gemm(x, w_in, h, NN, HID, FIN, 0);

    float* hcur = h;
    float* hnext = h2;
    const int ek_blocks = (EE*KH + 255) / 256;

    for (int layer = 0; layer < 2; layer++) {
        const float* wq = Wq + (size_t)layer * HID * (KH*DA);
        const float* wk = Wk + (size_t)layer * HID * (KH*DA);
        const float* wv = Wv + (size_t)layer * HID * (KH*DV);
        const float* wm = Wm + (size_t)layer * HID * DM;
        const float* wg = Wg + (size_t)layer * GATE_IN * KH;
        const float* wo = Wo + (size_t)layer * WO_IN * HID;

        init_layer_k<<<(NN*HID + 255) / 256, 256>>>(smax, denom, agg, maxpool, meansum, deg);

        launch_gemm(hcur, wq, q, NN, KH*DA, HID, 0);
        launch_gemm(hcur, wk, k, NN, KH*DA, HID, 0);
        launch_gemm(hcur, wv, v, NN, KH*DV, HID, 0);
        launch_gemm(hcur, wm, m, NN, DM,    HID, 0);

        edge_score_k<<<ek_blocks, 256>>>(q, k, src, dst, score, smax);
        edge_exp_k  <<<ek_blocks, 256>>>(score, smax, dst, denom);
        edge_agg_k  <<<ek_blocks, 256>>>(score, denom, v, src, dst, agg);
        edge_pool_k <<<(int)(((long long)EE*DM + 255) / 256), 256>>>(m, hcur, src, dst,
                                                                     maxpool, meansum, deg);

        gatein_k<<<(int)(((long long)NN*GATE_IN + 255) / 256), 256>>>(hcur, maxpool, meansum,
                                                                      deg, gatein);
        launch_gemm(gatein, wg, gate, NN, KH, GATE_IN, 2);  // sigmoid

        woin_k<<<(int)(((long long)NN*WO_IN + 255) / 256), 256>>>(hcur, gate, agg, woin);
        launch_gemm(woin, wo, hnext, NN, HID, WO_IN, 1);    // leaky_relu

        float* t = hcur; hcur = hnext; hnext = t;
    }

    // logits + log_softmax
    launch_gemm(hcur, w_out, logits, NN, NCLS, HID, 0);
    logsoftmax_k<<<(NN + 3) / 4, 128>>>(logits, out);
}

// round 3
// speedup vs baseline: 1.4773x; 1.4773x over previous
#include <cuda_runtime.h>
#include <math.h>

// ---------------- problem dims (fixed) ----------------
#define NN 50000
#define EE 600000
#define FIN 128
#define HID 128
#define KH 8
#define DA 16
#define DV 16
#define DM 64
#define NCLS 40
#define GATE_IN (HID + DM + HID)   // 320
#define WO_IN  (HID + KH*DV)       // 256
#define QKVM 448                   // fused q(128)|k(128)|v(128)|m(64)
#define SLOPE 0.1f

// ---------------- device scratch (no allocations allowed) ----------------
__device__ float g_h    [NN*HID];
__device__ float g_h2   [NN*HID];
__device__ float g_qkvm [NN*QKVM];
__device__ float g_wqkvm[HID*QKVM];
__device__ float g_score[EE*KH];       // reused as ex
__device__ float g_smax [NN*KH];
__device__ float g_denom[NN*KH];
__device__ float g_agg  [NN*KH*DV];
__device__ float g_maxpool[NN*DM];
__device__ float g_meansum[NN*HID];
__device__ float g_deg  [NN];
__device__ float g_gate [NN*KH];
__device__ float g_woin [NN*WO_IN];
__device__ float g_logits[NN*NCLS];

// ---------------- helpers ----------------
__device__ __forceinline__ void atomicMaxF(float* addr, float value) {
    if (value >= 0.0f) atomicMax((int*)addr, __float_as_int(value));
    else               atomicMin((unsigned int*)addr, __float_as_uint(value));
}

// ---------------- kernels ----------------
__global__ void init_layer_k(float* smax, float* denom, float* agg,
                             float* maxpool, float* meansum, float* deg) {
    int i = blockIdx.x * blockDim.x + threadIdx.x;
    if (i < NN*HID) { agg[i] = 0.f; meansum[i] = 0.f; }
    if (i < NN*DM)  maxpool[i] = -INFINITY;
    if (i < NN*KH)  { smax[i] = -INFINITY; denom[i] = 0.f; }
    if (i < NN)     deg[i] = 0.f;
}

// pack layer weights [128 x 448] = [Wq | Wk | Wv | Wm]
__global__ void pack_qkvm_k(const float* __restrict__ Wq, const float* __restrict__ Wk,
                            const float* __restrict__ Wv, const float* __restrict__ Wm,
                            float* __restrict__ Bf) {
    int idx = blockIdx.x * blockDim.x + threadIdx.x;
    if (idx >= HID*QKVM) return;
    int r = idx / QKVM, c = idx % QKVM;
    float v;
    if      (c < 128) v = Wq[r*128 + c];
    else if (c < 256) v = Wk[r*128 + (c-128)];
    else if (c < 384) v = Wv[r*128 + (c-256)];
    else              v = Wm[r*64  + (c-384)];
    Bf[idx] = v;
}

// ---------------- 128x128x8 SGEMM, 8x8 microtile, 256 threads ----------------
// C[M,Nc] = A[M,Kc] @ B[Kc,Nc], row-major. act: 0 none, 1 leaky_relu
// Requires: Kc % 8 == 0, Nc % 4 == 0.
__global__ __launch_bounds__(256, 2)
void sgemm128_k(const float* __restrict__ A, const float* __restrict__ B,
                float* __restrict__ C, int M, int Nc, int Kc, int act) {
    __shared__ float As[8][128];   // [k][m]
    __shared__ float Bs[8][128];   // [k][n]
    int tid = threadIdx.x;
    int tx = tid & 15, ty = tid >> 4;          // 16x16 thread grid
    int rowBase = blockIdx.y * 128;
    int colBase = blockIdx.x * 128;

    // A-load mapping: 128 rows x 8 cols, one float4 per thread
    int arow  = tid >> 1;
    int acol4 = (tid & 1) * 4;
    // B-load mapping: 8 rows x 128 cols, one float4 per thread
    int brow  = tid >> 5;
    int bcol4 = (tid & 31) * 4;

    float acc[8][8] = {};

    for (int k0 = 0; k0 < Kc; k0 += 8) {
        int gr = rowBase + arow;
        float4 av = make_float4(0.f, 0.f, 0.f, 0.f);
        if (gr < M) av = *(const float4*)(A + (size_t)gr*Kc + k0 + acol4);
        As[acol4+0][arow] = av.x;
        As[acol4+1][arow] = av.y;
        As[acol4+2][arow] = av.z;
        As[acol4+3][arow] = av.w;

        int gc = colBase + bcol4;
        float4 bv = make_float4(0.f, 0.f, 0.f, 0.f);
        if (gc < Nc) bv = *(const float4*)(B + (size_t)(k0+brow)*Nc + gc);
        *(float4*)&Bs[brow][bcol4] = bv;
        __syncthreads();

        #pragma unroll
        for (int kk = 0; kk < 8; kk++) {
            float4 a0 = *(const float4*)&As[kk][ty*4];
            float4 a1 = *(const float4*)&As[kk][64 + ty*4];
            float4 b0 = *(const float4*)&Bs[kk][tx*4];
            float4 b1 = *(const float4*)&Bs[kk][64 + tx*4];
            float a[8] = {a0.x,a0.y,a0.z,a0.w, a1.x,a1.y,a1.z,a1.w};
            float b[8] = {b0.x,b0.y,b0.z,b0.w, b1.x,b1.y,b1.z,b1.w};
            #pragma unroll
            for (int i = 0; i < 8; i++)
                #pragma unroll
                for (int j = 0; j < 8; j++)
                    acc[i][j] += a[i] * b[j];
        }
        __syncthreads();
    }

    #pragma unroll
    for (int ih = 0; ih < 2; ih++) {
        #pragma unroll
        for (int i = 0; i < 4; i++) {
            int gr = rowBase + ih*64 + ty*4 + i;
            if (gr >= M) continue;
            #pragma unroll
            for (int jh = 0; jh < 2; jh++) {
                int gc = colBase + jh*64 + tx*4;
                if (gc >= Nc) continue;
                float4 vv;
                vv.x = acc[ih*4+i][jh*4+0];
                vv.y = acc[ih*4+i][jh*4+1];
                vv.z = acc[ih*4+i][jh*4+2];
                vv.w = acc[ih*4+i][jh*4+3];
                if (act == 1) {
                    vv.x = vv.x > 0.f ? vv.x : SLOPE*vv.x;
                    vv.y = vv.y > 0.f ? vv.y : SLOPE*vv.y;
                    vv.z = vv.z > 0.f ? vv.z : SLOPE*vv.z;
                    vv.w = vv.w > 0.f ? vv.w : SLOPE*vv.w;
                }
                *(float4*)(C + (size_t)gr*Nc + gc) = vv;
            }
        }
    }
}

// ---------------- edge kernels (qkvm fused layout, node stride 448) ----------------
__global__ void edge_score_k(const float* __restrict__ qkvm,
                             const int* __restrict__ src, const int* __restrict__ dst,
                             float* __restrict__ score, float* __restrict__ smax) {
    int idx = blockIdx.x * blockDim.x + threadIdx.x;
    if (idx >= EE*KH) return;
    int e = idx >> 3, h = idx & 7;
    int s = src[e], d = dst[e];
    const float4* qa = (const float4*)(qkvm + (size_t)d*QKVM + h*DA);          // q
    const float4* ka = (const float4*)(qkvm + (size_t)s*QKVM + 128 + h*DA);    // k
    float acc = 0.f;
    #pragma unroll
    for (int i = 0; i < 4; i++) {
        float4 a = qa[i], b = ka[i];
        acc += a.x*b.x + a.y*b.y + a.z*b.z + a.w*b.w;
    }
    score[idx] = acc;
    atomicMaxF(&smax[d*KH + h], acc);
}

__global__ void edge_exp_k(float* __restrict__ score, const float* __restrict__ smax,
                           const int* __restrict__ dst, float* __restrict__ denom) {
    int idx = blockIdx.x * blockDim.x + threadIdx.x;
    if (idx >= EE*KH) return;
    int e = idx >> 3, h = idx & 7;
    int d = dst[e];
    float ex = expf(score[idx] - smax[d*KH + h]);
    score[idx] = ex;
    atomicAdd(&denom[d*KH + h], ex);
}

__global__ void edge_agg_k(const float* __restrict__ ex, const float* __restrict__ denom,
                           const float* __restrict__ qkvm,
                           const int* __restrict__ src, const int* __restrict__ dst,
                           float* __restrict__ agg) {
    int idx = blockIdx.x * blockDim.x + threadIdx.x;
    if (idx >= EE*KH) return;
    int e = idx >> 3, h = idx & 7;
    int s = src[e], d = dst[e];
    float alpha = ex[idx] / (denom[d*KH + h] + 1e-16f);
    const float4* vp = (const float4*)(qkvm + (size_t)s*QKVM + 256 + h*DV);    // v
    float* ap = agg + (size_t)d*(KH*DV) + h*DV;
    #pragma unroll
    for (int i = 0; i < 4; i++) {
        float4 vv = vp[i];
        atomicAdd(ap + i*4 + 0, alpha * vv.x);
        atomicAdd(ap + i*4 + 1, alpha * vv.y);
        atomicAdd(ap + i*4 + 2, alpha * vv.z);
        atomicAdd(ap + i*4 + 3, alpha * vv.w);
    }
}

__global__ void edge_pool_k(const float* __restrict__ qkvm, const float* __restrict__ h,
                            const int* __restrict__ src, const int* __restrict__ dst,
                            float* __restrict__ maxpool, float* __restrict__ meansum,
                            float* __restrict__ deg) {
    long long idx = (long long)blockIdx.x * blockDim.x + threadIdx.x;
    if (idx >= (long long)EE*DM) return;
    int e = (int)(idx >> 6), j = (int)(idx & 63);
    int s = src[e], d = dst[e];
    atomicMaxF(&maxpool[(size_t)d*DM + j], qkvm[(size_t)s*QKVM + 384 + j]);    // m
    atomicAdd(&meansum[(size_t)d*HID + j],      h[(size_t)s*HID + j]);
    atomicAdd(&meansum[(size_t)d*HID + 64 + j], h[(size_t)s*HID + 64 + j]);
    if (j == 0) atomicAdd(&deg[d], 1.0f);
}

// ---------------- gate: warp per node, Wg in padded smem ----------------
__global__ void gate_k(const float* __restrict__ h, const float* __restrict__ maxpool,
                       const float* __restrict__ meansum, const float* __restrict__ deg,
                       const float* __restrict__ Wg, float* __restrict__ gate) {
    __shared__ float Ws[GATE_IN][KH+1];     // pad to avoid bank conflicts
    int tid = threadIdx.x;                   // 256
    for (int i = tid; i < GATE_IN*KH; i += 256) Ws[i/KH][i%KH] = Wg[i];
    __syncthreads();
    int warp = tid >> 5, lane = tid & 31;
    int n = blockIdx.x * 8 + warp;
    if (n >= NN) return;
    float dg = fmaxf(deg[n], 1.0f);
    float acc[KH] = {};
    #pragma unroll
    for (int t = 0; t < 10; t++) {
        int j = lane + t*32;                 // 0..319
        float xv;
        if (j < HID) xv = h[(size_t)n*HID + j];
        else if (j < HID + DM) {
            float mp = maxpool[(size_t)n*DM + (j - HID)];
            xv = isfinite(mp) ? mp : 0.f;
        } else {
            xv = meansum[(size_t)n*HID + (j - HID - DM)] / dg;
        }
        #pragma unroll
        for (int o = 0; o < KH; o++) acc[o] += xv * Ws[j][o];
    }
    #pragma unroll
    for (int o = 0; o < KH; o++)
        #pragma unroll
        for (int off = 16; off; off >>= 1)
            acc[o] += __shfl_xor_sync(0xffffffffu, acc[o], off);
    if (lane < KH) gate[(size_t)n*KH + lane] = 1.f/(1.f + expf(-acc[lane]));
}

// wo_in = [h | g[n,head] * agg[n,head,d]]
__global__ void woin_k(const float* __restrict__ h, const float* __restrict__ g,
                       const float* __restrict__ agg, float* __restrict__ wi) {
    long long idx = (long long)blockIdx.x * blockDim.x + threadIdx.x;
    if (idx >= (long long)NN*WO_IN) return;
    int n = (int)(idx >> 8), j = (int)(idx & 255);
    float val;
    if (j < HID) val = h[(size_t)n*HID + j];
    else {
        int jj = j - HID;
        val = g[(size_t)n*KH + (jj >> 4)] * agg[(size_t)n*(KH*DV) + jj];
    }
    wi[idx] = val;
}

// row-wise log_softmax over 40 classes; one warp per row
__global__ void logsoftmax_k(const float* __restrict__ logits, float* __restrict__ out) {
    int row = blockIdx.x * 4 + (threadIdx.x >> 5);
    int lane = threadIdx.x & 31;
    if (row >= NN) return;
    const float* p = logits + (size_t)row * NCLS;
    float v0 = p[lane];
    float v1 = (lane < NCLS - 32) ? p[lane + 32] : -INFINITY;
    float mx = fmaxf(v0, v1);
    #pragma unroll
    for (int off = 16; off > 0; off >>= 1)
        mx = fmaxf(mx, __shfl_xor_sync(0xffffffffu, mx, off));
    float sm = expf(v0 - mx) + ((lane < NCLS - 32) ? expf(v1 - mx) : 0.f);
    #pragma unroll
    for (int off = 16; off > 0; off >>= 1)
        sm += __shfl_xor_sync(0xffffffffu, sm, off);
    float lse = mx + logf(sm);
    out[(size_t)row*NCLS + lane] = v0 - lse;
    if (lane < NCLS - 32) out[(size_t)row*NCLS + lane + 32] = v1 - lse;
}

// ---------------- host side ----------------
static inline void launch_gemm(const float* A, const float* B, float* C,
                               int M, int Nc, int Kc, int act) {
    dim3 grid((Nc + 127) / 128, (M + 127) / 128);
    sgemm128_k<<<grid, 256>>>(A, B, C, M, Nc, Kc, act);
}

extern "C" void kernel_launch(void* const* d_in, const int* in_sizes, int n_in,
                              void* d_out, int out_size) {
    const float* x     = (const float*)d_in[0];
    const int*   ei    = (const int*)d_in[1];      // int32 (JAX demotes int64)
    const float* w_in  = (const float*)d_in[2];
    const float* w_out = (const float*)d_in[3];
    const float* Wq    = (const float*)d_in[4];
    const float* Wk    = (const float*)d_in[5];
    const float* Wv    = (const float*)d_in[6];
    const float* Wm    = (const float*)d_in[7];
    const float* Wg    = (const float*)d_in[8];
    const float* Wo    = (const float*)d_in[9];
    float* out = (float*)d_out;

    const int* src = ei;
    const int* dst = ei + EE;

    float *h, *h2, *qkvm, *wqkvm, *score, *smax, *denom, *agg;
    float *maxpool, *meansum, *deg, *gate, *woin, *logits;
    cudaGetSymbolAddress((void**)&h,       g_h);
    cudaGetSymbolAddress((void**)&h2,      g_h2);
    cudaGetSymbolAddress((void**)&qkvm,    g_qkvm);
    cudaGetSymbolAddress((void**)&wqkvm,   g_wqkvm);
    cudaGetSymbolAddress((void**)&score,   g_score);
    cudaGetSymbolAddress((void**)&smax,    g_smax);
    cudaGetSymbolAddress((void**)&denom,   g_denom);
    cudaGetSymbolAddress((void**)&agg,     g_agg);
    cudaGetSymbolAddress((void**)&maxpool, g_maxpool);
    cudaGetSymbolAddress((void**)&meansum, g_meansum);
    cudaGetSymbolAddress((void**)&deg,     g_deg);
    cudaGetSymbolAddress((void**)&gate,    g_gate);
    cudaGetSymbolAddress((void**)&woin,    g_woin);
    cudaGetSymbolAddress((void**)&logits,  g_logits);

    // h = x @ weight_in
    launch_gemm(x, w_in, h, NN, HID, FIN, 0);

    float* hcur = h;
    float* hnext = h2;
    const int ek_blocks = (EE*KH + 255) / 256;

    for (int layer = 0; layer < 2; layer++) {
        const float* wq = Wq + (size_t)layer * HID * (KH*DA);
        const float* wk = Wk + (size_t)layer * HID * (KH*DA);
        const float* wv = Wv + (size_t)layer * HID * (KH*DV);
        const float* wm = Wm + (size_t)layer * HID * DM;
        const float* wg = Wg + (size_t)layer * GATE_IN * KH;
        const float* wo = Wo + (size_t)layer * WO_IN * HID;

        init_layer_k<<<(NN*HID + 255) / 256, 256>>>(smax, denom, agg, maxpool, meansum, deg);

        pack_qkvm_k<<<(HID*QKVM + 255) / 256, 256>>>(wq, wk, wv, wm, wqkvm);
        launch_gemm(hcur, wqkvm, qkvm, NN, QKVM, HID, 0);   // q|k|v|m in one GEMM

        edge_score_k<<<ek_blocks, 256>>>(qkvm, src, dst, score, smax);
        edge_exp_k  <<<ek_blocks, 256>>>(score, smax, dst, denom);
        edge_agg_k  <<<ek_blocks, 256>>>(score, denom, qkvm, src, dst, agg);
        edge_pool_k <<<(int)(((long long)EE*DM + 255) / 256), 256>>>(qkvm, hcur, src, dst,
                                                                     maxpool, meansum, deg);

        gate_k<<<(NN + 7) / 8, 256>>>(hcur, maxpool, meansum, deg, wg, gate);

        woin_k<<<(int)(((long long)NN*WO_IN + 255) / 256), 256>>>(hcur, gate, agg, woin);
        launch_gemm(woin, wo, hnext, NN, HID, WO_IN, 1);    // leaky_relu

        float* t = hcur; hcur = hnext; hnext = t;
    }

    // logits + log_softmax
    launch_gemm(hcur, w_out, logits, NN, NCLS, HID, 0);
    logsoftmax_k<<<(NN + 3) / 4, 128>>>(logits, out);
}

// round 4
// speedup vs baseline: 2.5668x; 1.7376x over previous
#include <cuda_runtime.h>
#include <math.h>

// ---------------- problem dims (fixed) ----------------
#define NN 50000
#define EE 600000
#define FIN 128
#define HID 128
#define KH 8
#define DA 16
#define DV 16
#define DM 64
#define NCLS 40
#define WO_IN  (HID + KH*DV)       // 256
#define QKVM 448                   // fused q(128)|k(128)|v(128)|m(64)
#define SLOPE 0.1f

// ---------------- device scratch (no allocations allowed) ----------------
__device__ float g_h    [NN*HID];
__device__ float g_h2   [NN*HID];
__device__ float g_qkvm [NN*QKVM];
__device__ float g_wqkvm[HID*QKVM];
__device__ float g_score[EE*KH];
__device__ float g_agg  [NN*KH*DV];
__device__ float g_maxpool[NN*DM];
__device__ float g_mean [NN*HID];
__device__ float g_gate [NN*KH];
__device__ float g_woin [NN*WO_IN];
__device__ float g_logits[NN*NCLS];
__device__ int   g_cnt   [NN];
__device__ int   g_rowptr[NN+1];
__device__ int   g_wptr  [NN];
__device__ int   g_esrc  [EE];

// ---------------- CSR build ----------------
__global__ void zero_cnt_k(int* cnt) {
    int i = blockIdx.x * blockDim.x + threadIdx.x;
    if (i < NN) cnt[i] = 0;
}
__global__ void hist_k(const int* __restrict__ dst, int* __restrict__ cnt) {
    int e = blockIdx.x * blockDim.x + threadIdx.x;
    if (e < EE) atomicAdd(&cnt[dst[e]], 1);
}
// single block, 1024 threads: chunked exclusive scan over NN
__global__ void scan_k(const int* __restrict__ cnt, int* __restrict__ rowptr,
                       int* __restrict__ wptr) {
    __shared__ int ps[1024];
    const int C = (NN + 1023) / 1024;
    int t = threadIdx.x;
    int base = t * C;
    int sum = 0;
    for (int j = 0; j < C; j++) {
        int idx = base + j;
        if (idx < NN) sum += cnt[idx];
    }
    ps[t] = sum; __syncthreads();
    for (int off = 1; off < 1024; off <<= 1) {
        int v = (t >= off) ? ps[t - off] : 0;
        __syncthreads();
        ps[t] += v;
        __syncthreads();
    }
    int running = ps[t] - sum;   // exclusive prefix for this chunk
    if (t == 0) rowptr[0] = 0;
    for (int j = 0; j < C; j++) {
        int idx = base + j;
        if (idx < NN) {
            wptr[idx] = running;
            running += cnt[idx];
            rowptr[idx + 1] = running;
        }
    }
}
__global__ void scatter_k(const int* __restrict__ src, const int* __restrict__ dst,
                          int* __restrict__ wptr, int* __restrict__ esrc) {
    int e = blockIdx.x * blockDim.x + threadIdx.x;
    if (e < EE) {
        int pos = atomicAdd(&wptr[dst[e]], 1);
        esrc[pos] = src[e];
    }
}

// pack layer weights [128 x 448] = [Wq | Wk | Wv | Wm]
__global__ void pack_qkvm_k(const float* __restrict__ Wq, const float* __restrict__ Wk,
                            const float* __restrict__ Wv, const float* __restrict__ Wm,
                            float* __restrict__ Bf) {
    int idx = blockIdx.x * blockDim.x + threadIdx.x;
    if (idx >= HID*QKVM) return;
    int r = idx / QKVM, c = idx % QKVM;
    float v;
    if      (c < 128) v = Wq[r*128 + c];
    else if (c < 256) v = Wk[r*128 + (c-128)];
    else if (c < 384) v = Wv[r*128 + (c-256)];
    else              v = Wm[r*64  + (c-384)];
    Bf[idx] = v;
}

// ---------------- 128x128x16 SGEMM, 8x8 microtile, 256 threads ----------------
// Requires: Kc % 16 == 0, Nc % 4 == 0.
__global__ __launch_bounds__(256, 2)
void sgemm128_k(const float* __restrict__ A, const float* __restrict__ B,
                float* __restrict__ C, int M, int Nc, int Kc, int act) {
    __shared__ float As[16][128];
    __shared__ float Bs[16][128];
    int tid = threadIdx.x;
    int tx = tid & 15, ty = tid >> 4;
    int rowBase = blockIdx.y * 128;
    int colBase = blockIdx.x * 128;

    int arow  = tid >> 1;
    int acol4 = (tid & 1) * 4;
    int brow  = tid >> 5;
    int bcol4 = (tid & 31) * 4;

    float acc[8][8] = {};

    for (int k0 = 0; k0 < Kc; k0 += 16) {
        int gr = rowBase + arow;
        #pragma unroll
        for (int half = 0; half < 2; half++) {
            int ac = acol4 + half * 8;
            float4 av = make_float4(0.f, 0.f, 0.f, 0.f);
            if (gr < M) av = *(const float4*)(A + (size_t)gr*Kc + k0 + ac);
            As[ac+0][arow] = av.x;
            As[ac+1][arow] = av.y;
            As[ac+2][arow] = av.z;
            As[ac+3][arow] = av.w;
        }
        int gc = colBase + bcol4;
        #pragma unroll
        for (int half = 0; half < 2; half++) {
            int br = brow + half * 8;
            float4 bv = make_float4(0.f, 0.f, 0.f, 0.f);
            if (gc < Nc) bv = *(const float4*)(B + (size_t)(k0+br)*Nc + gc);
            *(float4*)&Bs[br][bcol4] = bv;
        }
        __syncthreads();

        #pragma unroll
        for (int kk = 0; kk < 16; kk++) {
            float4 a0 = *(const float4*)&As[kk][ty*4];
            float4 a1 = *(const float4*)&As[kk][64 + ty*4];
            float4 b0 = *(const float4*)&Bs[kk][tx*4];
            float4 b1 = *(const float4*)&Bs[kk][64 + tx*4];
            float a[8] = {a0.x,a0.y,a0.z,a0.w, a1.x,a1.y,a1.z,a1.w};
            float b[8] = {b0.x,b0.y,b0.z,b0.w, b1.x,b1.y,b1.z,b1.w};
            #pragma unroll
            for (int i = 0; i < 8; i++)
                #pragma unroll
                for (int j = 0; j < 8; j++)
                    acc[i][j] += a[i] * b[j];
        }
        __syncthreads();
    }

    #pragma unroll
    for (int ih = 0; ih < 2; ih++) {
        #pragma unroll
        for (int i = 0; i < 4; i++) {
            int gr = rowBase + ih*64 + ty*4 + i;
            if (gr >= M) continue;
            #pragma unroll
            for (int jh = 0; jh < 2; jh++) {
                int gc = colBase + jh*64 + tx*4;
                if (gc >= Nc) continue;
                float4 vv;
                vv.x = acc[ih*4+i][jh*4+0];
                vv.y = acc[ih*4+i][jh*4+1];
                vv.z = acc[ih*4+i][jh*4+2];
                vv.w = acc[ih*4+i][jh*4+3];
                if (act == 1) {
                    vv.x = vv.x > 0.f ? vv.x : SLOPE*vv.x;
                    vv.y = vv.y > 0.f ? vv.y : SLOPE*vv.y;
                    vv.z = vv.z > 0.f ? vv.z : SLOPE*vv.z;
                    vv.w = vv.w > 0.f ? vv.w : SLOPE*vv.w;
                }
                *(float4*)(C + (size_t)gr*Nc + gc) = vv;
            }
        }
    }
}

// ---------------- attention: warp per node, CSR, no atomics ----------------
// lane = head*4 + sub; each lane owns 4 of 16 dims of its head.
__global__ __launch_bounds__(256)
void attn_k(const float* __restrict__ qkvm, const int* __restrict__ rowptr,
            const int* __restrict__ esrc, float* __restrict__ score,
            float* __restrict__ agg) {
    int warp = (blockIdx.x * blockDim.x + threadIdx.x) >> 5;
    int lane = threadIdx.x & 31;
    if (warp >= NN) return;
    int n = warp;
    int head = lane >> 2, sub = lane & 3;
    float4 q4 = *(const float4*)(qkvm + (size_t)n*QKVM + lane*4);   // q
    int start = rowptr[n], end = rowptr[n+1];

    float smx = -INFINITY;
    for (int i = start; i < end; i++) {
        int s = esrc[i];
        float4 k4 = *(const float4*)(qkvm + (size_t)s*QKVM + 128 + lane*4);
        float p = q4.x*k4.x + q4.y*k4.y + q4.z*k4.z + q4.w*k4.w;
        p += __shfl_xor_sync(0xffffffffu, p, 1);
        p += __shfl_xor_sync(0xffffffffu, p, 2);
        if (sub == 0) score[(size_t)i*KH + head] = p;
        smx = fmaxf(smx, p);
    }

    float denom = 0.f;
    float4 acc = make_float4(0.f, 0.f, 0.f, 0.f);
    for (int i = start; i < end; i++) {
        int s = esrc[i];
        float sc = score[(size_t)i*KH + head];
        float ex = __expf(sc - smx);
        denom += ex;
        float4 v4 = *(const float4*)(qkvm + (size_t)s*QKVM + 256 + lane*4);
        acc.x += ex*v4.x; acc.y += ex*v4.y; acc.z += ex*v4.z; acc.w += ex*v4.w;
    }
    float inv = 1.f / (denom + 1e-16f);
    float4 o = make_float4(acc.x*inv, acc.y*inv, acc.z*inv, acc.w*inv);
    *(float4*)(agg + (size_t)n*(KH*DV) + lane*4) = o;
}

// ---------------- pool: warp per node, CSR, no atomics ----------------
__global__ __launch_bounds__(256)
void pool_k(const float* __restrict__ qkvm, const float* __restrict__ h,
            const int* __restrict__ rowptr, const int* __restrict__ esrc,
            float* __restrict__ maxpool, float* __restrict__ mean) {
    int warp = (blockIdx.x * blockDim.x + threadIdx.x) >> 5;
    int lane = threadIdx.x & 31;
    if (warp >= NN) return;
    int n = warp;
    int start = rowptr[n], end = rowptr[n+1];
    int cnt = end - start;
    float mx0 = -INFINITY, mx1 = -INFINITY;
    float s0 = 0.f, s1 = 0.f, s2 = 0.f, s3 = 0.f;
    for (int i = start; i < end; i++) {
        int s = esrc[i];
        const float* mb = qkvm + (size_t)s*QKVM + 384;
        mx0 = fmaxf(mx0, mb[lane]);
        mx1 = fmaxf(mx1, mb[lane + 32]);
        const float* hb = h + (size_t)s*HID;
        s0 += hb[lane]; s1 += hb[lane+32]; s2 += hb[lane+64]; s3 += hb[lane+96];
    }
    float invd = 1.f / fmaxf((float)cnt, 1.f);
    maxpool[(size_t)n*DM + lane]      = cnt ? mx0 : 0.f;
    maxpool[(size_t)n*DM + 32 + lane] = cnt ? mx1 : 0.f;
    mean[(size_t)n*HID + lane]      = s0*invd;
    mean[(size_t)n*HID + 32 + lane] = s1*invd;
    mean[(size_t)n*HID + 64 + lane] = s2*invd;
    mean[(size_t)n*HID + 96 + lane] = s3*invd;
}

// ---------------- gate: warp per node, Wg in padded smem ----------------
#define GATE_IN 320
__global__ void gate_k(const float* __restrict__ h, const float* __restrict__ maxpool,
                       const float* __restrict__ mean, const float* __restrict__ Wg,
                       float* __restrict__ gate) {
    __shared__ float Ws[GATE_IN][KH+1];
    int tid = threadIdx.x;                   // 256
    for (int i = tid; i < GATE_IN*KH; i += 256) Ws[i/KH][i%KH] = Wg[i];
    __syncthreads();
    int warp = tid >> 5, lane = tid & 31;
    int n = blockIdx.x * 8 + warp;
    if (n >= NN) return;
    float acc[KH] = {};
    #pragma unroll
    for (int t = 0; t < 10; t++) {
        int j = lane + t*32;
        float xv;
        if (j < HID)            xv = h[(size_t)n*HID + j];
        else if (j < HID + DM)  xv = maxpool[(size_t)n*DM + (j - HID)];
        else                    xv = mean[(size_t)n*HID + (j - HID - DM)];
        #pragma unroll
        for (int o = 0; o < KH; o++) acc[o] += xv * Ws[j][o];
    }
    #pragma unroll
    for (int o = 0; o < KH; o++)
        #pragma unroll
        for (int off = 16; off; off >>= 1)
            acc[o] += __shfl_xor_sync(0xffffffffu, acc[o], off);
    if (lane < KH) gate[(size_t)n*KH + lane] = 1.f/(1.f + expf(-acc[lane]));
}

// wo_in = [h | g[n,head] * agg[n,head,d]]
__global__ void woin_k(const float* __restrict__ h, const float* __restrict__ g,
                       const float* __restrict__ agg, float* __restrict__ wi) {
    long long idx = (long long)blockIdx.x * blockDim.x + threadIdx.x;
    if (idx >= (long long)NN*WO_IN) return;
    int n = (int)(idx >> 8), j = (int)(idx & 255);
    float val;
    if (j < HID) val = h[(size_t)n*HID + j];
    else {
        int jj = j - HID;
        val = g[(size_t)n*KH + (jj >> 4)] * agg[(size_t)n*(KH*DV) + jj];
    }
    wi[idx] = val;
}

// row-wise log_softmax over 40 classes; one warp per row
__global__ void logsoftmax_k(const float* __restrict__ logits, float* __restrict__ out) {
    int row = blockIdx.x * 4 + (threadIdx.x >> 5);
    int lane = threadIdx.x & 31;
    if (row >= NN) return;
    const float* p = logits + (size_t)row * NCLS;
    float v0 = p[lane];
    float v1 = (lane < NCLS - 32) ? p[lane + 32] : -INFINITY;
    float mx = fmaxf(v0, v1);
    #pragma unroll
    for (int off = 16; off > 0; off >>= 1)
        mx = fmaxf(mx, __shfl_xor_sync(0xffffffffu, mx, off));
    float sm = expf(v0 - mx) + ((lane < NCLS - 32) ? expf(v1 - mx) : 0.f);
    #pragma unroll
    for (int off = 16; off > 0; off >>= 1)
        sm += __shfl_xor_sync(0xffffffffu, sm, off);
    float lse = mx + logf(sm);
    out[(size_t)row*NCLS + lane] = v0 - lse;
    if (lane < NCLS - 32) out[(size_t)row*NCLS + lane + 32] = v1 - lse;
}

// ---------------- host side ----------------
static inline void launch_gemm(const float* A, const float* B, float* C,
                               int M, int Nc, int Kc, int act) {
    dim3 grid((Nc + 127) / 128, (M + 127) / 128);
    sgemm128_k<<<grid, 256>>>(A, B, C, M, Nc, Kc, act);
}

extern "C" void kernel_launch(void* const* d_in, const int* in_sizes, int n_in,
                              void* d_out, int out_size) {
    const float* x     = (const float*)d_in[0];
    const int*   ei    = (const int*)d_in[1];      // int32 (JAX demotes int64)
    const float* w_in  = (const float*)d_in[2];
    const float* w_out = (const float*)d_in[3];
    const float* Wq    = (const float*)d_in[4];
    const float* Wk    = (const float*)d_in[5];
    const float* Wv    = (const float*)d_in[6];
    const float* Wm    = (const float*)d_in[7];
    const float* Wg    = (const float*)d_in[8];
    const float* Wo    = (const float*)d_in[9];
    float* out = (float*)d_out;

    const int* srcA = ei;
    const int* dstA = ei + EE;

    float *h, *h2, *qkvm, *wqkvm, *score, *agg, *maxpool, *mean, *gate, *woin, *logits;
    int *cnt, *rowptr, *wptr, *esrc;
    cudaGetSymbolAddress((void**)&h,       g_h);
    cudaGetSymbolAddress((void**)&h2,      g_h2);
    cudaGetSymbolAddress((void**)&qkvm,    g_qkvm);
    cudaGetSymbolAddress((void**)&wqkvm,   g_wqkvm);
    cudaGetSymbolAddress((void**)&score,   g_score);
    cudaGetSymbolAddress((void**)&agg,     g_agg);
    cudaGetSymbolAddress((void**)&maxpool, g_maxpool);
    cudaGetSymbolAddress((void**)&mean,    g_mean);
    cudaGetSymbolAddress((void**)&gate,    g_gate);
    cudaGetSymbolAddress((void**)&woin,    g_woin);
    cudaGetSymbolAddress((void**)&logits,  g_logits);
    cudaGetSymbolAddress((void**)&cnt,     g_cnt);
    cudaGetSymbolAddress((void**)&rowptr,  g_rowptr);
    cudaGetSymbolAddress((void**)&wptr,    g_wptr);
    cudaGetSymbolAddress((void**)&esrc,    g_esrc);

    // ---- CSR build (once per call, reused across layers) ----
    zero_cnt_k<<<(NN + 255) / 256, 256>>>(cnt);
    hist_k<<<(EE + 255) / 256, 256>>>(dstA, cnt);
    scan_k<<<1, 1024>>>(cnt, rowptr, wptr);
    scatter_k<<<(EE + 255) / 256, 256>>>(srcA, dstA, wptr, esrc);

    // h = x @ weight_in
    launch_gemm(x, w_in, h, NN, HID, FIN, 0);

    float* hcur = h;
    float* hnext = h2;

    for (int layer = 0; layer < 2; layer++) {
        const float* wq = Wq + (size_t)layer * HID * (KH*DA);
        const float* wk = Wk + (size_t)layer * HID * (KH*DA);
        const float* wv = Wv + (size_t)layer * HID * (KH*DV);
        const float* wm = Wm + (size_t)layer * HID * DM;
        const float* wg = Wg + (size_t)layer * GATE_IN * KH;
        const float* wo = Wo + (size_t)layer * WO_IN * HID;

        pack_qkvm_k<<<(HID*QKVM + 255) / 256, 256>>>(wq, wk, wv, wm, wqkvm);
        launch_gemm(hcur, wqkvm, qkvm, NN, QKVM, HID, 0);   // q|k|v|m fused

        attn_k<<<(NN*32 + 255) / 256, 256>>>(qkvm, rowptr, esrc, score, agg);
        pool_k<<<(NN*32 + 255) / 256, 256>>>(qkvm, hcur, rowptr, esrc, maxpool, mean);
        gate_k<<<(NN + 7) / 8, 256>>>(hcur, maxpool, mean, wg, gate);

        woin_k<<<(int)(((long long)NN*WO_IN + 255) / 256), 256>>>(hcur, gate, agg, woin);
        launch_gemm(woin, wo, hnext, NN, HID, WO_IN, 1);    // leaky_relu

        float* t = hcur; hcur = hnext; hnext = t;
    }

    // logits + log_softmax
    launch_gemm(hcur, w_out, logits, NN, NCLS, HID, 0);
    logsoftmax_k<<<(NN + 3) / 4, 128>>>(logits, out);
}

// round 6
// speedup vs baseline: 2.8421x; 1.1073x over previous
#include <cuda_runtime.h>
#include <math.h>

// ---------------- problem dims (fixed) ----------------
#define NN 50000
#define EE 600000
#define FIN 128
#define HID 128
#define KH 8
#define DA 16
#define DV 16
#define DM 64
#define NCLS 40
#define WO_IN  (HID + KH*DV)       // 256
#define QKVM 448                   // fused q(128)|k(128)|v(128)|m(64)
#define GATE_IN 320
#define SLOPE 0.1f

// ---------------- device scratch (no allocations allowed) ----------------
__device__ float g_h    [NN*HID];
__device__ float g_h2   [NN*HID];
__device__ float g_qkvm [(size_t)NN*QKVM];
__device__ float g_wqkvm[HID*QKVM];
__device__ float g_woin [NN*WO_IN];
__device__ float g_logits[NN*NCLS];
__device__ int   g_cnt   [NN];
__device__ int   g_rowptr[NN+1];
__device__ int   g_wptr  [NN];
__device__ int   g_esrc  [EE];

// ---------------- CSR build ----------------
__global__ void zero_cnt_k(int* cnt) {
    int i = blockIdx.x * blockDim.x + threadIdx.x;
    if (i < NN) cnt[i] = 0;
}
__global__ void hist_k(const int* __restrict__ dst, int* __restrict__ cnt) {
    int e = blockIdx.x * blockDim.x + threadIdx.x;
    if (e < EE) atomicAdd(&cnt[dst[e]], 1);
}
__global__ void scan_k(const int* __restrict__ cnt, int* __restrict__ rowptr,
                       int* __restrict__ wptr) {
    __shared__ int ps[1024];
    const int C = (NN + 1023) / 1024;
    int t = threadIdx.x;
    int base = t * C;
    int sum = 0;
    for (int j = 0; j < C; j++) {
        int idx = base + j;
        if (idx < NN) sum += cnt[idx];
    }
    ps[t] = sum; __syncthreads();
    for (int off = 1; off < 1024; off <<= 1) {
        int v = (t >= off) ? ps[t - off] : 0;
        __syncthreads();
        ps[t] += v;
        __syncthreads();
    }
    int running = ps[t] - sum;
    if (t == 0) rowptr[0] = 0;
    for (int j = 0; j < C; j++) {
        int idx = base + j;
        if (idx < NN) {
            wptr[idx] = running;
            running += cnt[idx];
            rowptr[idx + 1] = running;
        }
    }
}
__global__ void scatter_k(const int* __restrict__ src, const int* __restrict__ dst,
                          int* __restrict__ wptr, int* __restrict__ esrc) {
    int e = blockIdx.x * blockDim.x + threadIdx.x;
    if (e < EE) {
        int pos = atomicAdd(&wptr[dst[e]], 1);
        esrc[pos] = src[e];
    }
}

// pack layer weights [128 x 448] = [Wq | Wk | Wv | Wm]
__global__ void pack_qkvm_k(const float* __restrict__ Wq, const float* __restrict__ Wk,
                            const float* __restrict__ Wv, const float* __restrict__ Wm,
                            float* __restrict__ Bf) {
    int idx = blockIdx.x * blockDim.x + threadIdx.x;
    if (idx >= HID*QKVM) return;
    int r = idx / QKVM, c = idx % QKVM;
    float v;
    if      (c < 128) v = Wq[r*128 + c];
    else if (c < 256) v = Wk[r*128 + (c-128)];
    else if (c < 384) v = Wv[r*128 + (c-256)];
    else              v = Wm[r*64  + (c-384)];
    Bf[idx] = v;
}

// ---------------- 128x128x16 SGEMM, 8x8 microtile, double-buffered ----------------
// Requires: Kc % 16 == 0, Nc % 4 == 0.
__global__ __launch_bounds__(256, 2)
void sgemm128_k(const float* __restrict__ A, const float* __restrict__ B,
                float* __restrict__ C, int M, int Nc, int Kc, int act) {
    __shared__ float As[2][16][128];
    __shared__ float Bs[2][16][128];
    int tid = threadIdx.x;
    int tx = tid & 15, ty = tid >> 4;
    int rowBase = blockIdx.y * 128;
    int colBase = blockIdx.x * 128;

    int arow  = tid >> 1;
    int acol4 = (tid & 1) * 4;
    int brow  = tid >> 5;
    int bcol4 = (tid & 31) * 4;
    int agr = rowBase + arow;
    int bgc = colBase + bcol4;

    float4 pa[2], pb[2];

    // preload chunk 0
    #pragma unroll
    for (int half = 0; half < 2; half++) {
        int ac = acol4 + half * 8;
        pa[half] = make_float4(0.f, 0.f, 0.f, 0.f);
        if (agr < M) pa[half] = *(const float4*)(A + (size_t)agr*Kc + ac);
        pb[half] = make_float4(0.f, 0.f, 0.f, 0.f);
        if (bgc < Nc) pb[half] = *(const float4*)(B + (size_t)(brow + half*8)*Nc + bgc);
    }
    #pragma unroll
    for (int half = 0; half < 2; half++) {
        int ac = acol4 + half * 8;
        As[0][ac+0][arow] = pa[half].x;
        As[0][ac+1][arow] = pa[half].y;
        As[0][ac+2][arow] = pa[half].z;
        As[0][ac+3][arow] = pa[half].w;
        *(float4*)&Bs[0][brow + half*8][bcol4] = pb[half];
    }
    __syncthreads();

    float acc[8][8] = {};
    int nchunks = Kc >> 4;

    for (int c = 0; c < nchunks; c++) {
        int cur = c & 1;
        // issue loads for next chunk
        if (c + 1 < nchunks) {
            int k0 = (c + 1) << 4;
            #pragma unroll
            for (int half = 0; half < 2; half++) {
                int ac = acol4 + half * 8;
                pa[half] = make_float4(0.f, 0.f, 0.f, 0.f);
                if (agr < M) pa[half] = *(const float4*)(A + (size_t)agr*Kc + k0 + ac);
                pb[half] = make_float4(0.f, 0.f, 0.f, 0.f);
                if (bgc < Nc) pb[half] = *(const float4*)(B + (size_t)(k0 + brow + half*8)*Nc + bgc);
            }
        }
        // compute current chunk
        #pragma unroll
        for (int kk = 0; kk < 16; kk++) {
            float4 a0 = *(const float4*)&As[cur][kk][ty*4];
            float4 a1 = *(const float4*)&As[cur][kk][64 + ty*4];
            float4 b0 = *(const float4*)&Bs[cur][kk][tx*4];
            float4 b1 = *(const float4*)&Bs[cur][kk][64 + tx*4];
            float a[8] = {a0.x,a0.y,a0.z,a0.w, a1.x,a1.y,a1.z,a1.w};
            float b[8] = {b0.x,b0.y,b0.z,b0.w, b1.x,b1.y,b1.z,b1.w};
            #pragma unroll
            for (int i = 0; i < 8; i++)
                #pragma unroll
                for (int j = 0; j < 8; j++)
                    acc[i][j] += a[i] * b[j];
        }
        // store next chunk into other buffer
        if (c + 1 < nchunks) {
            int nxt = cur ^ 1;
            #pragma unroll
            for (int half = 0; half < 2; half++) {
                int ac = acol4 + half * 8;
                As[nxt][ac+0][arow] = pa[half].x;
                As[nxt][ac+1][arow] = pa[half].y;
                As[nxt][ac+2][arow] = pa[half].z;
                As[nxt][ac+3][arow] = pa[half].w;
                *(float4*)&Bs[nxt][brow + half*8][bcol4] = pb[half];
            }
        }
        __syncthreads();
    }

    #pragma unroll
    for (int ih = 0; ih < 2; ih++) {
        #pragma unroll
        for (int i = 0; i < 4; i++) {
            int gr = rowBase + ih*64 + ty*4 + i;
            if (gr >= M) continue;
            #pragma unroll
            for (int jh = 0; jh < 2; jh++) {
                int gc = colBase + jh*64 + tx*4;
                if (gc >= Nc) continue;
                float4 vv;
                vv.x = acc[ih*4+i][jh*4+0];
                vv.y = acc[ih*4+i][jh*4+1];
                vv.z = acc[ih*4+i][jh*4+2];
                vv.w = acc[ih*4+i][jh*4+3];
                if (act == 1) {
                    vv.x = vv.x > 0.f ? vv.x : SLOPE*vv.x;
                    vv.y = vv.y > 0.f ? vv.y : SLOPE*vv.y;
                    vv.z = vv.z > 0.f ? vv.z : SLOPE*vv.z;
                    vv.w = vv.w > 0.f ? vv.w : SLOPE*vv.w;
                }
                *(float4*)(C + (size_t)gr*Nc + gc) = vv;
            }
        }
    }
}

// ---------------- fully fused node kernel: attn+pool+gate+woin ----------------
// warp per node; online softmax; all reductions in registers; writes woin row.
__global__ __launch_bounds__(256)
void node_fused_k(const float* __restrict__ qkvm, const float* __restrict__ h,
                  const int* __restrict__ rowptr, const int* __restrict__ esrc,
                  const float* __restrict__ Wg, float* __restrict__ woin) {
    __shared__ float Ws[GATE_IN][KH+1];   // padded: conflict-free
    int tid = threadIdx.x;                // 256
    for (int i = tid; i < GATE_IN*KH; i += 256) Ws[i/KH][i%KH] = Wg[i];
    __syncthreads();

    int warp = tid >> 5, lane = tid & 31;
    int n = blockIdx.x * 8 + warp;
    if (n >= NN) return;

    float4 q4 = *(const float4*)(qkvm + (size_t)n*QKVM + lane*4);   // q
    int start = rowptr[n], end = rowptr[n+1];
    int cnt = end - start;

    float smx = -INFINITY, denom = 0.f;
    float4 acc = make_float4(0.f, 0.f, 0.f, 0.f);
    float mx0 = -INFINITY, mx1 = -INFINITY;
    float s0 = 0.f, s1 = 0.f, s2 = 0.f, s3 = 0.f;

    for (int i = start; i < end; i++) {
        int s = esrc[i];
        const float* base = qkvm + (size_t)s*QKVM;
        float4 k4 = *(const float4*)(base + 128 + lane*4);
        float p = q4.x*k4.x + q4.y*k4.y + q4.z*k4.z + q4.w*k4.w;
        p += __shfl_xor_sync(0xffffffffu, p, 1);
        p += __shfl_xor_sync(0xffffffffu, p, 2);
        // online softmax update (per head; all 4 lanes of a head agree on p)
        float newmx = fmaxf(smx, p);
        float scale = __expf(smx - newmx);   // exp(-inf)=0 handles first edge
        float ex = __expf(p - newmx);
        denom = denom * scale + ex;
        float4 v4 = *(const float4*)(base + 256 + lane*4);
        acc.x = acc.x*scale + ex*v4.x;
        acc.y = acc.y*scale + ex*v4.y;
        acc.z = acc.z*scale + ex*v4.z;
        acc.w = acc.w*scale + ex*v4.w;
        smx = newmx;
        // pools
        mx0 = fmaxf(mx0, base[384 + lane]);
        mx1 = fmaxf(mx1, base[384 + 32 + lane]);
        const float* hb = h + (size_t)s*HID;
        s0 += hb[lane]; s1 += hb[lane+32]; s2 += hb[lane+64]; s3 += hb[lane+96];
    }

    float inv = 1.f / (denom + 1e-16f);
    float4 o = make_float4(acc.x*inv, acc.y*inv, acc.z*inv, acc.w*inv);  // agg

    float mp0 = cnt ? mx0 : 0.f, mp1 = cnt ? mx1 : 0.f;
    float invd = 1.f / fmaxf((float)cnt, 1.f);
    float me0 = s0*invd, me1 = s1*invd, me2 = s2*invd, me3 = s3*invd;

    // own h values
    const float* hn = h + (size_t)n*HID;
    float hv0 = hn[lane], hv1 = hn[lane+32], hv2 = hn[lane+64], hv3 = hn[lane+96];

    // gate FC: each lane contributes 10 of the 320 inputs
    float ga[KH] = {};
    {
        struct { int j; float v; } c10[10] = {
            {lane,        hv0}, {lane+32,  hv1}, {lane+64,  hv2}, {lane+96,  hv3},
            {128+lane,    mp0}, {160+lane, mp1},
            {192+lane,    me0}, {224+lane, me1}, {256+lane, me2}, {288+lane, me3}
        };
        #pragma unroll
        for (int t = 0; t < 10; t++) {
            float xv = c10[t].v;
            const float* wrow = &Ws[c10[t].j][0];
            #pragma unroll
            for (int oo = 0; oo < KH; oo++) ga[oo] += xv * wrow[oo];
        }
    }
    #pragma unroll
    for (int oo = 0; oo < KH; oo++)
        #pragma unroll
        for (int off = 16; off; off >>= 1)
            ga[oo] += __shfl_xor_sync(0xffffffffu, ga[oo], off);

    int head = lane >> 2;
    float gsum = ga[0];
    #pragma unroll
    for (int oo = 1; oo < KH; oo++) if (head == oo) gsum = ga[oo];
    float gh = 1.f / (1.f + expf(-gsum));

    // write woin row: [h | g*agg]
    float* w = woin + (size_t)n*WO_IN;
    w[lane] = hv0; w[lane+32] = hv1; w[lane+64] = hv2; w[lane+96] = hv3;
    *(float4*)(w + 128 + lane*4) = make_float4(gh*o.x, gh*o.y, gh*o.z, gh*o.w);
}

// row-wise log_softmax over 40 classes; one warp per row
__global__ void logsoftmax_k(const float* __restrict__ logits, float* __restrict__ out) {
    int row = blockIdx.x * 4 + (threadIdx.x >> 5);
    int lane = threadIdx.x & 31;
    if (row >= NN) return;
    const float* p = logits + (size_t)row * NCLS;
    float v0 = p[lane];
    float v1 = (lane < NCLS - 32) ? p[lane + 32] : -INFINITY;
    float mx = fmaxf(v0, v1);
    #pragma unroll
    for (int off = 16; off > 0; off >>= 1)
        mx = fmaxf(mx, __shfl_xor_sync(0xffffffffu, mx, off));
    float sm = expf(v0 - mx) + ((lane < NCLS - 32) ? expf(v1 - mx) : 0.f);
    #pragma unroll
    for (int off = 16; off > 0; off >>= 1)
        sm += __shfl_xor_sync(0xffffffffu, sm, off);
    float lse = mx + logf(sm);
    out[(size_t)row*NCLS + lane] = v0 - lse;
    if (lane < NCLS - 32) out[(size_t)row*NCLS + lane + 32] = v1 - lse;
}

// ---------------- host side ----------------
static inline void launch_gemm(const float* A, const float* B, float* C,
                               int M, int Nc, int Kc, int act) {
    dim3 grid((Nc + 127) / 128, (M + 127) / 128);
    sgemm128_k<<<grid, 256>>>(A, B, C, M, Nc, Kc, act);
}

extern "C" void kernel_launch(void* const* d_in, const int* in_sizes, int n_in,
                              void* d_out, int out_size) {
    const float* x     = (const float*)d_in[0];
    const int*   ei    = (const int*)d_in[1];      // int32 (JAX demotes int64)
    const float* w_in  = (const float*)d_in[2];
    const float* w_out = (const float*)d_in[3];
    const float* Wq    = (const float*)d_in[4];
    const float* Wk    = (const float*)d_in[5];
    const float* Wv    = (const float*)d_in[6];
    const float* Wm    = (const float*)d_in[7];
    const float* Wg    = (const float*)d_in[8];
    const float* Wo    = (const float*)d_in[9];
    float* out = (float*)d_out;

    const int* srcA = ei;
    const int* dstA = ei + EE;

    float *h, *h2, *qkvm, *wqkvm, *woin, *logits;
    int *cnt, *rowptr, *wptr, *esrc;
    cudaGetSymbolAddress((void**)&h,      g_h);
    cudaGetSymbolAddress((void**)&h2,     g_h2);
    cudaGetSymbolAddress((void**)&qkvm,   g_qkvm);
    cudaGetSymbolAddress((void**)&wqkvm,  g_wqkvm);
    cudaGetSymbolAddress((void**)&woin,   g_woin);
    cudaGetSymbolAddress((void**)&logits, g_logits);
    cudaGetSymbolAddress((void**)&cnt,    g_cnt);
    cudaGetSymbolAddress((void**)&rowptr, g_rowptr);
    cudaGetSymbolAddress((void**)&wptr,   g_wptr);
    cudaGetSymbolAddress((void**)&esrc,   g_esrc);

    // ---- CSR build (once per call, reused across layers) ----
    zero_cnt_k<<<(NN + 255) / 256, 256>>>(cnt);
    hist_k<<<(EE + 255) / 256, 256>>>(dstA, cnt);
    scan_k<<<1, 1024>>>(cnt, rowptr, wptr);
    scatter_k<<<(EE + 255) / 256, 256>>>(srcA, dstA, wptr, esrc);

    // h = x @ weight_in
    launch_gemm(x, w_in, h, NN, HID, FIN, 0);

    float* hcur = h;
    float* hnext = h2;

    for (int layer = 0; layer < 2; layer++) {
        const float* wq = Wq + (size_t)layer * HID * (KH*DA);
        const float* wk = Wk + (size_t)layer * HID * (KH*DA);
        const float* wv = Wv + (size_t)layer * HID * (KH*DV);
        const float* wm = Wm + (size_t)layer * HID * DM;
        const float* wg = Wg + (size_t)layer * GATE_IN * KH;
        const float* wo = Wo + (size_t)layer * WO_IN * HID;

        pack_qkvm_k<<<(HID*QKVM + 255) / 256, 256>>>(wq, wk, wv, wm, wqkvm);
        launch_gemm(hcur, wqkvm, qkvm, NN, QKVM, HID, 0);   // q|k|v|m fused

        node_fused_k<<<(NN + 7) / 8, 256>>>(qkvm, hcur, rowptr, esrc, wg, woin);

        launch_gemm(woin, wo, hnext, NN, HID, WO_IN, 1);    // leaky_relu

        float* t = hcur; hcur = hnext; hnext = t;
    }

    // logits + log_softmax
    launch_gemm(hcur, w_out, logits, NN, NCLS, HID, 0);
    logsoftmax_k<<<(NN + 3) / 4, 128>>>(logits, out);
}

// round 7
// speedup vs baseline: 3.5308x; 1.2423x over previous
#include <cuda_runtime.h>
#include <math.h>

// ---------------- problem dims (fixed) ----------------
#define NN 50000
#define EE 600000
#define FIN 128
#define HID 128
#define KH 8
#define DA 16
#define DV 16
#define DM 64
#define NCLS 40
#define WO_IN  (HID + KH*DV)       // 256
#define QS2 464                    // q(128)|k(128)|v(128)|m(64)|gx(8)|gm(8)
#define SLOPE 0.1f

// ---------------- device scratch (no allocations allowed) ----------------
__device__ float g_h    [NN*HID];
__device__ float g_h2   [NN*HID];
__device__ float g_qkvm [(size_t)NN*QS2];
__device__ float g_wqkvm[HID*QS2];
__device__ float g_woin [NN*WO_IN];
__device__ float g_logits[NN*NCLS];
__device__ int   g_cnt   [NN];
__device__ int   g_rowptr[NN+1];
__device__ int   g_wptr  [NN];
__device__ int   g_esrc  [EE];

// ---------------- f32x2 packed helpers ----------------
__device__ __forceinline__ unsigned long long fma2(unsigned long long a,
                                                   unsigned long long b,
                                                   unsigned long long c) {
    unsigned long long d;
    asm("fma.rn.f32x2 %0, %1, %2, %3;" : "=l"(d) : "l"(a), "l"(b), "l"(c));
    return d;
}
__device__ __forceinline__ unsigned long long dup2(float x) {
    unsigned long long d;
    asm("mov.b64 %0, {%1, %1};" : "=l"(d) : "f"(x));
    return d;
}
__device__ __forceinline__ void unpk2(unsigned long long d, float& lo, float& hi) {
    asm("mov.b64 {%0, %1}, %2;" : "=f"(lo), "=f"(hi) : "l"(d));
}

// ---------------- CSR build ----------------
__global__ void zero_cnt_k(int* cnt) {
    int i = blockIdx.x * blockDim.x + threadIdx.x;
    if (i < NN) cnt[i] = 0;
}
__global__ void hist_k(const int* __restrict__ dst, int* __restrict__ cnt) {
    int e = blockIdx.x * blockDim.x + threadIdx.x;
    if (e < EE) atomicAdd(&cnt[dst[e]], 1);
}
__global__ void scan_k(const int* __restrict__ cnt, int* __restrict__ rowptr,
                       int* __restrict__ wptr) {
    __shared__ int ps[1024];
    const int C = (NN + 1023) / 1024;
    int t = threadIdx.x;
    int base = t * C;
    int sum = 0;
    for (int j = 0; j < C; j++) {
        int idx = base + j;
        if (idx < NN) sum += cnt[idx];
    }
    ps[t] = sum; __syncthreads();
    for (int off = 1; off < 1024; off <<= 1) {
        int v = (t >= off) ? ps[t - off] : 0;
        __syncthreads();
        ps[t] += v;
        __syncthreads();
    }
    int running = ps[t] - sum;
    if (t == 0) rowptr[0] = 0;
    for (int j = 0; j < C; j++) {
        int idx = base + j;
        if (idx < NN) {
            wptr[idx] = running;
            running += cnt[idx];
            rowptr[idx + 1] = running;
        }
    }
}
__global__ void scatter_k(const int* __restrict__ src, const int* __restrict__ dst,
                          int* __restrict__ wptr, int* __restrict__ esrc) {
    int e = blockIdx.x * blockDim.x + threadIdx.x;
    if (e < EE) {
        int pos = atomicAdd(&wptr[dst[e]], 1);
        esrc[pos] = src[e];
    }
}

// pack layer weights [128 x 464] = [Wq | Wk | Wv | Wm | Wg_x | Wg_mean]
__global__ void pack_qkvm_k(const float* __restrict__ Wq, const float* __restrict__ Wk,
                            const float* __restrict__ Wv, const float* __restrict__ Wm,
                            const float* __restrict__ Wg, float* __restrict__ Bf) {
    int idx = blockIdx.x * blockDim.x + threadIdx.x;
    if (idx >= HID*QS2) return;
    int r = idx / QS2, c = idx % QS2;
    float v;
    if      (c < 128) v = Wq[r*128 + c];
    else if (c < 256) v = Wk[r*128 + (c-128)];
    else if (c < 384) v = Wv[r*128 + (c-256)];
    else if (c < 448) v = Wm[r*64  + (c-384)];
    else if (c < 456) v = Wg[r*KH + (c-448)];            // x rows of Wg
    else              v = Wg[(192 + r)*KH + (c-456)];    // mean rows of Wg
    Bf[idx] = v;
}

// ---------------- 128x128x16 SGEMM, 8x8 microtile, f32x2, double-buffered ----
// Requires: Kc % 16 == 0, Nc % 4 == 0.
__global__ __launch_bounds__(256, 2)
void sgemm128_k(const float* __restrict__ A, const float* __restrict__ B,
                float* __restrict__ C, int M, int Nc, int Kc, int act) {
    __shared__ float As[2][16][128];
    __shared__ float Bs[2][16][128];
    int tid = threadIdx.x;
    int tx = tid & 15, ty = tid >> 4;
    int rowBase = blockIdx.y * 128;
    int colBase = blockIdx.x * 128;

    int arow  = tid >> 1;
    int acol4 = (tid & 1) * 4;
    int brow  = tid >> 5;
    int bcol4 = (tid & 31) * 4;
    int agr = rowBase + arow;
    int bgc = colBase + bcol4;

    float4 pa[2], pb[2];

    #pragma unroll
    for (int half = 0; half < 2; half++) {
        int ac = acol4 + half * 8;
        pa[half] = make_float4(0.f, 0.f, 0.f, 0.f);
        if (agr < M) pa[half] = *(const float4*)(A + (size_t)agr*Kc + ac);
        pb[half] = make_float4(0.f, 0.f, 0.f, 0.f);
        if (bgc < Nc) pb[half] = *(const float4*)(B + (size_t)(brow + half*8)*Nc + bgc);
    }
    #pragma unroll
    for (int half = 0; half < 2; half++) {
        int ac = acol4 + half * 8;
        As[0][ac+0][arow] = pa[half].x;
        As[0][ac+1][arow] = pa[half].y;
        As[0][ac+2][arow] = pa[half].z;
        As[0][ac+3][arow] = pa[half].w;
        *(float4*)&Bs[0][brow + half*8][bcol4] = pb[half];
    }
    __syncthreads();

    unsigned long long acc2[8][4];
    #pragma unroll
    for (int i = 0; i < 8; i++)
        #pragma unroll
        for (int j = 0; j < 4; j++) acc2[i][j] = 0ull;

    int nchunks = Kc >> 4;
    for (int c = 0; c < nchunks; c++) {
        int cur = c & 1;
        if (c + 1 < nchunks) {
            int k0 = (c + 1) << 4;
            #pragma unroll
            for (int half = 0; half < 2; half++) {
                int ac = acol4 + half * 8;
                pa[half] = make_float4(0.f, 0.f, 0.f, 0.f);
                if (agr < M) pa[half] = *(const float4*)(A + (size_t)agr*Kc + k0 + ac);
                pb[half] = make_float4(0.f, 0.f, 0.f, 0.f);
                if (bgc < Nc) pb[half] = *(const float4*)(B + (size_t)(k0 + brow + half*8)*Nc + bgc);
            }
        }
        #pragma unroll
        for (int kk = 0; kk < 16; kk++) {
            float4 a0 = *(const float4*)&As[cur][kk][ty*4];
            float4 a1 = *(const float4*)&As[cur][kk][64 + ty*4];
            const unsigned long long* bp0 = (const unsigned long long*)&Bs[cur][kk][tx*4];
            const unsigned long long* bp1 = (const unsigned long long*)&Bs[cur][kk][64 + tx*4];
            unsigned long long b2[4] = {bp0[0], bp0[1], bp1[0], bp1[1]};
            float a[8] = {a0.x,a0.y,a0.z,a0.w, a1.x,a1.y,a1.z,a1.w};
            #pragma unroll
            for (int i = 0; i < 8; i++) {
                unsigned long long ad = dup2(a[i]);
                acc2[i][0] = fma2(ad, b2[0], acc2[i][0]);
                acc2[i][1] = fma2(ad, b2[1], acc2[i][1]);
                acc2[i][2] = fma2(ad, b2[2], acc2[i][2]);
                acc2[i][3] = fma2(ad, b2[3], acc2[i][3]);
            }
        }
        if (c + 1 < nchunks) {
            int nxt = cur ^ 1;
            #pragma unroll
            for (int half = 0; half < 2; half++) {
                int ac = acol4 + half * 8;
                As[nxt][ac+0][arow] = pa[half].x;
                As[nxt][ac+1][arow] = pa[half].y;
                As[nxt][ac+2][arow] = pa[half].z;
                As[nxt][ac+3][arow] = pa[half].w;
                *(float4*)&Bs[nxt][brow + half*8][bcol4] = pb[half];
            }
        }
        __syncthreads();
    }

    #pragma unroll
    for (int ih = 0; ih < 2; ih++) {
        #pragma unroll
        for (int i = 0; i < 4; i++) {
            int gr = rowBase + ih*64 + ty*4 + i;
            if (gr >= M) continue;
            #pragma unroll
            for (int jh = 0; jh < 2; jh++) {
                int gc = colBase + jh*64 + tx*4;
                if (gc >= Nc) continue;
                float4 vv;
                unpk2(acc2[ih*4+i][jh*2+0], vv.x, vv.y);
                unpk2(acc2[ih*4+i][jh*2+1], vv.z, vv.w);
                if (act == 1) {
                    vv.x = vv.x > 0.f ? vv.x : SLOPE*vv.x;
                    vv.y = vv.y > 0.f ? vv.y : SLOPE*vv.y;
                    vv.z = vv.z > 0.f ? vv.z : SLOPE*vv.z;
                    vv.w = vv.w > 0.f ? vv.w : SLOPE*vv.w;
                }
                *(float4*)(C + (size_t)gr*Nc + gc) = vv;
            }
        }
    }
}

// ---------------- fused node kernel: attn+pool+gate+woin ----------------
// warp per node; online softmax; gate via precomputed gx/gm projections.
__global__ __launch_bounds__(256)
void node_fused_k(const float* __restrict__ qkvm, const float* __restrict__ h,
                  const int* __restrict__ rowptr, const int* __restrict__ esrc,
                  const float* __restrict__ Wg, float* __restrict__ woin) {
    __shared__ float Ws[DM][KH+1];        // maxpool rows of Wg (64x8), padded
    int tid = threadIdx.x;                // 256
    for (int i = tid; i < DM*KH; i += 256) Ws[i/KH][i%KH] = Wg[(128 + i/KH)*KH + (i%KH)];
    __syncthreads();

    int warp = tid >> 5, lane = tid & 31;
    int n = blockIdx.x * 8 + warp;
    if (n >= NN) return;
    int head = lane >> 2;

    float4 q4 = *(const float4*)(qkvm + (size_t)n*QS2 + lane*4);   // q
    int start = rowptr[n], end = rowptr[n+1];
    int cnt = end - start;

    float smx = -INFINITY, denom = 0.f;
    float4 acc = make_float4(0.f, 0.f, 0.f, 0.f);
    float mx0 = -INFINITY, mx1 = -INFINITY;
    float gmsum = 0.f;                    // sum of gm[head] over neighbors

    for (int i = start; i < end; i++) {
        int s = esrc[i];
        const float* base = qkvm + (size_t)s*QS2;
        float4 k4 = *(const float4*)(base + 128 + lane*4);
        float p = q4.x*k4.x + q4.y*k4.y + q4.z*k4.z + q4.w*k4.w;
        p += __shfl_xor_sync(0xffffffffu, p, 1);
        p += __shfl_xor_sync(0xffffffffu, p, 2);
        float newmx = fmaxf(smx, p);
        float scale = __expf(smx - newmx);
        float ex = __expf(p - newmx);
        denom = denom * scale + ex;
        float4 v4 = *(const float4*)(base + 256 + lane*4);
        acc.x = acc.x*scale + ex*v4.x;
        acc.y = acc.y*scale + ex*v4.y;
        acc.z = acc.z*scale + ex*v4.z;
        acc.w = acc.w*scale + ex*v4.w;
        smx = newmx;
        mx0 = fmaxf(mx0, base[384 + lane]);
        mx1 = fmaxf(mx1, base[416 + lane]);
        gmsum += base[456 + head];
    }

    float inv = 1.f / (denom + 1e-16f);
    float4 o = make_float4(acc.x*inv, acc.y*inv, acc.z*inv, acc.w*inv);  // agg

    float mp0 = cnt ? mx0 : 0.f, mp1 = cnt ? mx1 : 0.f;
    float invd = 1.f / fmaxf((float)cnt, 1.f);

    // gate FC over maxpool (64 dims spread over lanes)
    float ga[KH] = {};
    #pragma unroll
    for (int oo = 0; oo < KH; oo++)
        ga[oo] = mp0 * Ws[lane][oo] + mp1 * Ws[lane + 32][oo];
    #pragma unroll
    for (int oo = 0; oo < KH; oo++)
        #pragma unroll
        for (int off = 16; off; off >>= 1)
            ga[oo] += __shfl_xor_sync(0xffffffffu, ga[oo], off);

    float gsum = ga[0];
    #pragma unroll
    for (int oo = 1; oo < KH; oo++) if (head == oo) gsum = ga[oo];
    gsum += qkvm[(size_t)n*QS2 + 448 + head];    // x part of gate
    gsum += gmsum * invd;                        // mean part of gate
    float gh = 1.f / (1.f + expf(-gsum));

    // write woin row: [h | g*agg]
    const float* hn = h + (size_t)n*HID;
    float* w = woin + (size_t)n*WO_IN;
    w[lane]    = hn[lane];
    w[lane+32] = hn[lane+32];
    w[lane+64] = hn[lane+64];
    w[lane+96] = hn[lane+96];
    *(float4*)(w + 128 + lane*4) = make_float4(gh*o.x, gh*o.y, gh*o.z, gh*o.w);
}

// row-wise log_softmax over 40 classes; one warp per row
__global__ void logsoftmax_k(const float* __restrict__ logits, float* __restrict__ out) {
    int row = blockIdx.x * 4 + (threadIdx.x >> 5);
    int lane = threadIdx.x & 31;
    if (row >= NN) return;
    const float* p = logits + (size_t)row * NCLS;
    float v0 = p[lane];
    float v1 = (lane < NCLS - 32) ? p[lane + 32] : -INFINITY;
    float mx = fmaxf(v0, v1);
    #pragma unroll
    for (int off = 16; off > 0; off >>= 1)
        mx = fmaxf(mx, __shfl_xor_sync(0xffffffffu, mx, off));
    float sm = expf(v0 - mx) + ((lane < NCLS - 32) ? expf(v1 - mx) : 0.f);
    #pragma unroll
    for (int off = 16; off > 0; off >>= 1)
        sm += __shfl_xor_sync(0xffffffffu, sm, off);
    float lse = mx + logf(sm);
    out[(size_t)row*NCLS + lane] = v0 - lse;
    if (lane < NCLS - 32) out[(size_t)row*NCLS + lane + 32] = v1 - lse;
}

// ---------------- host side ----------------
static inline void launch_gemm(const float* A, const float* B, float* C,
                               int M, int Nc, int Kc, int act) {
    dim3 grid((Nc + 127) / 128, (M + 127) / 128);
    sgemm128_k<<<grid, 256>>>(A, B, C, M, Nc, Kc, act);
}

extern "C" void kernel_launch(void* const* d_in, const int* in_sizes, int n_in,
                              void* d_out, int out_size) {
    const float* x     = (const float*)d_in[0];
    const int*   ei    = (const int*)d_in[1];      // int32 (JAX demotes int64)
    const float* w_in  = (const float*)d_in[2];
    const float* w_out = (const float*)d_in[3];
    const float* Wq    = (const float*)d_in[4];
    const float* Wk    = (const float*)d_in[5];
    const float* Wv    = (const float*)d_in[6];
    const float* Wm    = (const float*)d_in[7];
    const float* Wg    = (const float*)d_in[8];
    const float* Wo    = (const float*)d_in[9];
    float* out = (float*)d_out;

    const int* srcA = ei;
    const int* dstA = ei + EE;

    float *h, *h2, *qkvm, *wqkvm, *woin, *logits;
    int *cnt, *rowptr, *wptr, *esrc;
    cudaGetSymbolAddress((void**)&h,      g_h);
    cudaGetSymbolAddress((void**)&h2,     g_h2);
    cudaGetSymbolAddress((void**)&qkvm,   g_qkvm);
    cudaGetSymbolAddress((void**)&wqkvm,  g_wqkvm);
    cudaGetSymbolAddress((void**)&woin,   g_woin);
    cudaGetSymbolAddress((void**)&logits, g_logits);
    cudaGetSymbolAddress((void**)&cnt,    g_cnt);
    cudaGetSymbolAddress((void**)&rowptr, g_rowptr);
    cudaGetSymbolAddress((void**)&wptr,   g_wptr);
    cudaGetSymbolAddress((void**)&esrc,   g_esrc);

    // ---- CSR build (once per call, reused across layers) ----
    zero_cnt_k<<<(NN + 255) / 256, 256>>>(cnt);
    hist_k<<<(EE + 255) / 256, 256>>>(dstA, cnt);
    scan_k<<<1, 1024>>>(cnt, rowptr, wptr);
    scatter_k<<<(EE + 255) / 256, 256>>>(srcA, dstA, wptr, esrc);

    // h = x @ weight_in
    launch_gemm(x, w_in, h, NN, HID, FIN, 0);

    float* hcur = h;
    float* hnext = h2;

    for (int layer = 0; layer < 2; layer++) {
        const float* wq = Wq + (size_t)layer * HID * (KH*DA);
        const float* wk = Wk + (size_t)layer * HID * (KH*DA);
        const float* wv = Wv + (size_t)layer * HID * (KH*DV);
        const float* wm = Wm + (size_t)layer * HID * DM;
        const float* wg = Wg + (size_t)layer * 320 * KH;
        const float* wo = Wo + (size_t)layer * WO_IN * HID;

        pack_qkvm_k<<<(HID*QS2 + 255) / 256, 256>>>(wq, wk, wv, wm, wg, wqkvm);
        launch_gemm(hcur, wqkvm, qkvm, NN, QS2, HID, 0);    // q|k|v|m|gx|gm fused

        node_fused_k<<<(NN + 7) / 8, 256>>>(qkvm, hcur, rowptr, esrc, wg, woin);

        launch_gemm(woin, wo, hnext, NN, HID, WO_IN, 1);    // leaky_relu

        float* t = hcur; hcur = hnext; hnext = t;
    }

    // logits + log_softmax
    launch_gemm(hcur, w_out, logits, NN, NCLS, HID, 0);
    logsoftmax_k<<<(NN + 3) / 4, 128>>>(logits, out);
}